// round 1
// baseline (speedup 1.0000x reference)
#include <cuda_runtime.h>
#include <math.h>

// Problem shapes (fixed by setup_inputs)
#define BB   32
#define HS   96
#define WS   128
#define HL   768
#define WL   1024
#define KSZ  49
#define PADK 24
#define NT   768          // threads for k1

// smem layout (floats)
#define OFF_IN   0            // 96*129 = 12384 (s_in uses 12288, later reused as s_out)
#define OFF_T    12384        // 128*97 = 12416 (transposed vertical result)
#define OFF_KRAW 24800        // 49
#define OFF_KERN 24849        // 49
#define OFF_RED  24898        // 32
#define OFF_M    24930        // 1
#define SMEM_FLOATS 24931
#define SMEM_BYTES  (SMEM_FLOATS * 4)

__device__ float g_small[BB * HS * WS];
__device__ float g_logZ[BB];

__device__ __forceinline__ int clampi(int v, int hi) {
    return min(max(v, 0), hi);
}

__global__ void __launch_bounds__(NT, 1)
k1_blur_combine(const float* __restrict__ readout,
                const float* __restrict__ centerbias,
                const float* __restrict__ scaling,
                const int*   __restrict__ didx,
                const float* __restrict__ dsig,
                const float* __restrict__ dcbw,
                const float* __restrict__ dps,
                int nd)
{
    extern __shared__ float sm[];
    float* s_in   = sm + OFF_IN;
    float* s_out  = sm + OFF_IN;    // aliases s_in: input dead after vertical pass
    float* s_T    = sm + OFF_T;
    float* s_kraw = sm + OFF_KRAW;
    float* s_kern = sm + OFF_KERN;
    float* s_red  = sm + OFF_RED;
    float* s_M    = sm + OFF_M;

    const int tid = threadIdx.x;
    const int b   = blockIdx.x;

    // ---- load readout image into smem ----
    const float* rin = readout + (size_t)b * HS * WS;
    for (int i = tid; i < HS * WS; i += NT) s_in[i] = rin[i];

    // ---- per-batch scalars ----
    const int   d     = didx[b];
    const float sigma = dsig[d] * scaling[b];
    float mean = 0.f;
    for (int j = 0; j < nd; ++j) mean += dps[j];
    mean /= (float)nd;
    const float prio = expf(dps[d] - mean);
    const float cbw  = dcbw[d];

    // ---- gaussian kernel (normalized) ----
    if (tid < KSZ) {
        float g = ((float)tid - (float)(KSZ - 1) * 0.5f) / sigma;
        s_kraw[tid] = expf(-0.5f * g * g);
    }
    __syncthreads();
    if (tid < KSZ) {
        float s = 0.f;
        #pragma unroll
        for (int t = 0; t < KSZ; ++t) s += s_kraw[t];
        s_kern[tid] = s_kraw[tid] / s;
    }
    __syncthreads();

    // ---- vertical blur: s_in -> s_T (transposed, stride 97) ----
    {
        const int x     = tid & (WS - 1);
        const int grp   = tid >> 7;          // 0..5
        const int ybase = grp * 16;
        #pragma unroll
        for (int q = 0; q < 4; ++q) {
            const int y0   = ybase + q * 4;
            const int base = y0 - PADK;
            float a0 = 0.f, a1 = 0.f, a2 = 0.f, a3 = 0.f;
            float p1 = 0.f, p2 = 0.f, p3 = 0.f;
            #pragma unroll
            for (int t = 0; t < KSZ + 3; ++t) {
                const float kin = (t < KSZ) ? s_kern[t] : 0.f;
                const int   r   = clampi(base + t, HS - 1);
                const float v   = s_in[r * WS + x];
                a0 = fmaf(kin, v, a0);
                a1 = fmaf(p1,  v, a1);
                a2 = fmaf(p2,  v, a2);
                a3 = fmaf(p3,  v, a3);
                p3 = p2; p2 = p1; p1 = kin;
            }
            s_T[x * 97 + y0 + 0] = a0;
            s_T[x * 97 + y0 + 1] = a1;
            s_T[x * 97 + y0 + 2] = a2;
            s_T[x * 97 + y0 + 3] = a3;
        }
    }
    __syncthreads();

    // ---- horizontal blur + prio/centerbias combine ----
    float vloc[16];
    {
        const int yv    = tid % HS;         // 96 = 3 warps -> warp stays in one group
        const int gx    = tid / HS;         // 0..7
        const int xbase = gx * 16;
        const float* cbrow = centerbias + (size_t)b * HL * WL + (size_t)yv * 8 * WL;
        #pragma unroll
        for (int q = 0; q < 4; ++q) {
            const int x0   = xbase + q * 4;
            const int base = x0 - PADK;
            float a0 = 0.f, a1 = 0.f, a2 = 0.f, a3 = 0.f;
            float p1 = 0.f, p2 = 0.f, p3 = 0.f;
            #pragma unroll
            for (int t = 0; t < KSZ + 3; ++t) {
                const float kin = (t < KSZ) ? s_kern[t] : 0.f;
                const int   r   = clampi(base + t, WS - 1);
                const float v   = s_T[r * 97 + yv];
                a0 = fmaf(kin, v, a0);
                a1 = fmaf(p1,  v, a1);
                a2 = fmaf(p2,  v, a2);
                a3 = fmaf(p3,  v, a3);
                p3 = p2; p2 = p1; p1 = kin;
            }
            #pragma unroll
            for (int j = 0; j < 4; ++j) {
                const float z = (j == 0) ? a0 : (j == 1) ? a1 : (j == 2) ? a2 : a3;
                const int   x = x0 + j;
                const float cb  = cbrow[x * 8];
                const float val = fmaf(z, prio, cbw * cb);
                vloc[q * 4 + j] = val;
                s_out[yv * 129 + x] = val;   // safe: s_in dead after sync above
            }
        }
    }

    // ---- block-wide logsumexp (deterministic tree reduce) ----
    const int lane = tid & 31;
    const int wid  = tid >> 5;               // 24 warps

    float m = -INFINITY;
    #pragma unroll
    for (int i = 0; i < 16; ++i) m = fmaxf(m, vloc[i]);
    #pragma unroll
    for (int o = 16; o; o >>= 1) m = fmaxf(m, __shfl_xor_sync(0xFFFFFFFFu, m, o));
    if (lane == 0) s_red[wid] = m;
    __syncthreads();                         // also fences s_out writes
    if (wid == 0) {
        float mm = (lane < NT / 32) ? s_red[lane] : -INFINITY;
        #pragma unroll
        for (int o = 16; o; o >>= 1) mm = fmaxf(mm, __shfl_xor_sync(0xFFFFFFFFu, mm, o));
        if (lane == 0) s_M[0] = mm;
    }
    __syncthreads();
    const float M = s_M[0];

    float s = 0.f;
    #pragma unroll
    for (int i = 0; i < 16; ++i) s += expf(vloc[i] - M);
    #pragma unroll
    for (int o = 16; o; o >>= 1) s += __shfl_xor_sync(0xFFFFFFFFu, s, o);
    if (lane == 0) s_red[wid] = s;
    __syncthreads();
    if (wid == 0) {
        float ss = (lane < NT / 32) ? s_red[lane] : 0.f;
        #pragma unroll
        for (int o = 16; o; o >>= 1) ss += __shfl_xor_sync(0xFFFFFFFFu, ss, o);
        if (lane == 0)
            g_logZ[b] = M + logf(ss) + 4.1588830833596715f; // + log(64)
    }

    // ---- coalesced store of small result ----
    for (int i = tid; i < HS * WS; i += NT) {
        const int y = i >> 7, x = i & (WS - 1);
        g_small[(size_t)b * HS * WS + i] = s_out[y * 129 + x];
    }
}

// Upsample 8x8 + subtract logZ. Each thread: 8 consecutive outputs (2x float4).
__global__ void __launch_bounds__(256)
k2_upsample(float4* __restrict__ out)
{
    const int idx = blockIdx.x * 256 + threadIdx.x;     // 0 .. 32*768*128-1
    const int b   = idx / (HL * (WL / 8));              // / 98304
    const int rem = idx - b * (HL * (WL / 8));
    const int Y   = rem >> 7;                           // / 128
    const int Xg  = rem & 127;                          // X/8

    const float val = g_small[(size_t)b * HS * WS + ((Y >> 3) << 7) + Xg] - g_logZ[b];
    const float4 f = make_float4(val, val, val, val);
    const size_t o = (((size_t)(b * HL + Y) * WL) + (size_t)Xg * 8) >> 2;
    out[o]     = f;
    out[o + 1] = f;
}

extern "C" void kernel_launch(void* const* d_in, const int* in_sizes, int n_in,
                              void* d_out, int out_size)
{
    const float* readout    = (const float*)d_in[0];
    const float* centerbias = (const float*)d_in[1];
    const float* scaling    = (const float*)d_in[2];
    const int*   didx       = (const int*)  d_in[3];
    const float* dsig       = (const float*)d_in[4];
    const float* dcbw       = (const float*)d_in[5];
    const float* dps        = (const float*)d_in[6];
    const int    nd         = in_sizes[4];
    float* out = (float*)d_out;

    cudaFuncSetAttribute(k1_blur_combine,
                         cudaFuncAttributeMaxDynamicSharedMemorySize, SMEM_BYTES);

    k1_blur_combine<<<BB, NT, SMEM_BYTES>>>(readout, centerbias, scaling,
                                            didx, dsig, dcbw, dps, nd);

    const int groups = BB * HL * (WL / 8);   // 3,145,728
    k2_upsample<<<groups / 256, 256>>>((float4*)out);
}

// round 2
// speedup vs baseline: 1.3402x; 1.3402x over previous
#include <cuda_runtime.h>
#include <math.h>

// Problem shapes (fixed by setup_inputs)
#define BB   32
#define HS   96
#define WS   128
#define HL   768
#define WL   1024
#define KSZ  49
#define PADK 24
#define LOG64 4.1588830833596715f

__device__ float g_T[BB * HS * WS];      // vertical-blur result, [b][y][x]
__device__ float g_small[BB * HS * WS];  // combined small-res result
__device__ float g_pm[BB * 4];           // per-strip max
__device__ float g_ps[BB * 4];           // per-strip sum(exp(v - max))

__device__ __forceinline__ int clampi(int v, int hi) {
    return min(max(v, 0), hi);
}

// Build normalized Gaussian kernel in smem (s_k), using s_kr as scratch.
__device__ __forceinline__ void build_kernel(float* s_kr, float* s_k,
                                             float sigma, int tid)
{
    if (tid < KSZ) {
        float g = ((float)tid - (float)(KSZ - 1) * 0.5f) / sigma;
        s_kr[tid] = expf(-0.5f * g * g);
    }
    __syncthreads();
    if (tid < KSZ) {
        float s = 0.f;
        #pragma unroll
        for (int t = 0; t < KSZ; ++t) s += s_kr[t];
        s_k[tid] = s_kr[tid] / s;
    }
    __syncthreads();
}

// ---------------------------------------------------------------------------
// k1a: vertical blur. grid = BB*4, block handles (b, 32-column strip).
// ---------------------------------------------------------------------------
#define NT1 256
__global__ void __launch_bounds__(NT1, 4)
k1a_vblur(const float* __restrict__ readout,
          const float* __restrict__ scaling,
          const int*   __restrict__ didx,
          const float* __restrict__ dsig)
{
    __shared__ float s_in[HS * 32];
    __shared__ float s_kr[KSZ];
    __shared__ float s_k[KSZ];

    const int tid = threadIdx.x;
    const int b   = blockIdx.x >> 2;
    const int x0  = (blockIdx.x & 3) * 32;

    // load strip: 96 rows x 32 cols (128B per row, coalesced)
    const float* rin = readout + (size_t)b * HS * WS + x0;
    for (int i = tid; i < HS * 32; i += NT1) {
        const int r = i >> 5, c = i & 31;
        s_in[i] = rin[r * WS + c];
    }

    const float sigma = dsig[didx[b]] * scaling[b];
    build_kernel(s_kr, s_k, sigma, tid);   // includes syncthreads (covers s_in)

    // conv: thread = (xl = tid&31, g0 = tid>>5), 3 row-groups of 4
    const int xl = tid & 31;
    const int g0 = tid >> 5;
    float* gout = g_T + (size_t)b * HS * WS + x0 + xl;
    #pragma unroll
    for (int q = 0; q < 3; ++q) {
        const int y0   = (g0 + q * 8) * 4;
        const int base = y0 - PADK;
        float a0 = 0.f, a1 = 0.f, a2 = 0.f, a3 = 0.f;
        float p1 = 0.f, p2 = 0.f, p3 = 0.f;
        #pragma unroll
        for (int t = 0; t < KSZ + 3; ++t) {
            const float kin = (t < KSZ) ? s_k[t] : 0.f;
            const int   r   = clampi(base + t, HS - 1);
            const float v   = s_in[r * 32 + xl];
            a0 = fmaf(kin, v, a0);
            a1 = fmaf(p1,  v, a1);
            a2 = fmaf(p2,  v, a2);
            a3 = fmaf(p3,  v, a3);
            p3 = p2; p2 = p1; p1 = kin;
        }
        gout[(y0 + 0) * WS] = a0;
        gout[(y0 + 1) * WS] = a1;
        gout[(y0 + 2) * WS] = a2;
        gout[(y0 + 3) * WS] = a3;
    }
}

// ---------------------------------------------------------------------------
// k1b: horizontal blur + combine + partial LSE. grid = BB*4,
// block handles (b, 24-row strip).
// ---------------------------------------------------------------------------
#define NT2 384
__global__ void __launch_bounds__(NT2, 2)
k1b_hblur(const float* __restrict__ centerbias,
          const float* __restrict__ scaling,
          const int*   __restrict__ didx,
          const float* __restrict__ dsig,
          const float* __restrict__ dcbw,
          const float* __restrict__ dps,
          int nd)
{
    __shared__ float s_row[24 * 129];
    __shared__ float s_kr[KSZ];
    __shared__ float s_k[KSZ];
    __shared__ float s_red[NT2 / 32];

    const int tid = threadIdx.x;
    const int b   = blockIdx.x >> 2;
    const int s4  = blockIdx.x & 3;
    const int y0  = s4 * 24;

    // load 24 rows x 128 cols from g_T
    const float* tin = g_T + (size_t)b * HS * WS + (size_t)y0 * WS;
    for (int i = tid; i < 24 * WS; i += NT2) {
        const int r = i >> 7, c = i & (WS - 1);
        s_row[r * 129 + c] = tin[r * WS + c];
    }

    const int   d     = didx[b];
    const float sigma = dsig[d] * scaling[b];
    float mean = 0.f;
    for (int j = 0; j < nd; ++j) mean += dps[j];
    mean /= (float)nd;
    const float prio = expf(dps[d] - mean);
    const float cbw  = dcbw[d];

    build_kernel(s_kr, s_k, sigma, tid);   // syncthreads covers s_row load

    // items: 24 rows x 32 col-groups = 768; thread does 2
    float vloc[8];
    #pragma unroll
    for (int q = 0; q < 2; ++q) {
        const int w    = tid + q * NT2;
        const int row  = w % 24;
        const int xb   = (w / 24) * 4;
        const int base = xb - PADK;
        float a0 = 0.f, a1 = 0.f, a2 = 0.f, a3 = 0.f;
        float p1 = 0.f, p2 = 0.f, p3 = 0.f;
        #pragma unroll
        for (int t = 0; t < KSZ + 3; ++t) {
            const float kin = (t < KSZ) ? s_k[t] : 0.f;
            const int   r   = clampi(base + t, WS - 1);
            const float v   = s_row[row * 129 + r];
            a0 = fmaf(kin, v, a0);
            a1 = fmaf(p1,  v, a1);
            a2 = fmaf(p2,  v, a2);
            a3 = fmaf(p3,  v, a3);
            p3 = p2; p2 = p1; p1 = kin;
        }
        const int yg = y0 + row;
        const float* cbrow = centerbias + (size_t)b * HL * WL + (size_t)yg * 8 * WL;
        float* sml = g_small + (size_t)b * HS * WS + (size_t)yg * WS;
        #pragma unroll
        for (int j = 0; j < 4; ++j) {
            const float z  = (j == 0) ? a0 : (j == 1) ? a1 : (j == 2) ? a2 : a3;
            const int   x  = xb + j;
            const float cb = cbrow[x * 8];
            const float val = fmaf(z, prio, cbw * cb);
            vloc[q * 4 + j] = val;
            sml[x] = val;
        }
    }

    // partial LSE over this strip (deterministic tree)
    const int lane = tid & 31;
    const int wid  = tid >> 5;

    float m = -INFINITY;
    #pragma unroll
    for (int i = 0; i < 8; ++i) m = fmaxf(m, vloc[i]);
    #pragma unroll
    for (int o = 16; o; o >>= 1) m = fmaxf(m, __shfl_xor_sync(0xFFFFFFFFu, m, o));
    if (lane == 0) s_red[wid] = m;
    __syncthreads();
    if (wid == 0) {
        float mm = (lane < NT2 / 32) ? s_red[lane] : -INFINITY;
        #pragma unroll
        for (int o = 16; o; o >>= 1) mm = fmaxf(mm, __shfl_xor_sync(0xFFFFFFFFu, mm, o));
        if (lane == 0) s_red[0] = mm;
    }
    __syncthreads();
    const float M = s_red[0];
    __syncthreads();

    float s = 0.f;
    #pragma unroll
    for (int i = 0; i < 8; ++i) s += expf(vloc[i] - M);
    #pragma unroll
    for (int o = 16; o; o >>= 1) s += __shfl_xor_sync(0xFFFFFFFFu, s, o);
    if (lane == 0) s_red[wid] = s;
    __syncthreads();
    if (wid == 0) {
        float ss = (lane < NT2 / 32) ? s_red[lane] : 0.f;
        #pragma unroll
        for (int o = 16; o; o >>= 1) ss += __shfl_xor_sync(0xFFFFFFFFu, ss, o);
        if (lane == 0) {
            g_pm[b * 4 + s4] = M;
            g_ps[b * 4 + s4] = ss;
        }
    }
}

// ---------------------------------------------------------------------------
// k2: upsample 8x8 + subtract logZ. grid = BB*HS = 3072 blocks;
// block (b, source row Ys); each thread owns one float4 column, writes it to
// 8 output rows — every warp store is 512B contiguous.
// ---------------------------------------------------------------------------
__global__ void __launch_bounds__(256)
k2_upsample(float4* __restrict__ out)
{
    const int tid = threadIdx.x;
    const int b   = blockIdx.x / HS;
    const int Ys  = blockIdx.x - b * HS;

    // finalize logZ from the 4 strip partials (redundant per block, cheap)
    float M = g_pm[b * 4];
    #pragma unroll
    for (int i = 1; i < 4; ++i) M = fmaxf(M, g_pm[b * 4 + i]);
    float Z = 0.f;
    #pragma unroll
    for (int i = 0; i < 4; ++i) Z += g_ps[b * 4 + i] * expf(g_pm[b * 4 + i] - M);
    const float logZ = M + logf(Z) + LOG64;

    // thread tid covers output float4 column tid: X = 4*tid, source x = tid>>1
    const float v = g_small[(size_t)b * HS * WS + Ys * WS + (tid >> 1)] - logZ;
    const float4 f = make_float4(v, v, v, v);

    const size_t base = ((size_t)(b * HL + Ys * 8) * WL) >> 2;   // float4 units
    #pragma unroll
    for (int k = 0; k < 8; ++k)
        out[base + (size_t)k * (WL / 4) + tid] = f;
}

extern "C" void kernel_launch(void* const* d_in, const int* in_sizes, int n_in,
                              void* d_out, int out_size)
{
    const float* readout    = (const float*)d_in[0];
    const float* centerbias = (const float*)d_in[1];
    const float* scaling    = (const float*)d_in[2];
    const int*   didx       = (const int*)  d_in[3];
    const float* dsig       = (const float*)d_in[4];
    const float* dcbw       = (const float*)d_in[5];
    const float* dps        = (const float*)d_in[6];
    const int    nd         = in_sizes[4];
    float* out = (float*)d_out;

    k1a_vblur<<<BB * 4, NT1>>>(readout, scaling, didx, dsig);
    k1b_hblur<<<BB * 4, NT2>>>(centerbias, scaling, didx, dsig, dcbw, dps, nd);
    k2_upsample<<<BB * HS, 256>>>((float4*)out);
}